// round 17
// baseline (speedup 1.0000x reference)
#include <cuda_runtime.h>
#include <cuda_fp16.h>
#include <math.h>

#define BATCH 8
#define SEQ   8192
#define DIM   512
#define HEADS 8
#define DH    64
#define SL    32
#define MTOT  (BATCH * SEQ)
#define KV_SPLITS 64
#define QDIM  (HEADS * SL)        // 256

// ---------------- device scratch ----------------
__device__ __half  g_xh  [(size_t)MTOT * DIM];
__device__ __half  g_qh  [(size_t)MTOT * QDIM];
__device__ float   g_S1p [(size_t)KV_SPLITS * 64 * SL * DH];
__device__ float   g_S0p [(size_t)KV_SPLITS * 64 * SL];
__device__ __half  g_Wp  [(size_t)DIM * DIM];           // W_in, k-paired fp16
__device__ __half  g_Zp  [(size_t)BATCH * QDIM * DIM];  // Z, k-paired fp16
__device__ __half2 g_WC  [(size_t)32 * 128];            // [Wq|Wk|Wv] k-paired fp16

__device__ __forceinline__ void mma_f16(float* c, const unsigned* a, const unsigned* b) {
    asm volatile(
        "mma.sync.aligned.m16n8k16.row.col.f32.f16.f16.f32 "
        "{%0,%1,%2,%3}, {%4,%5,%6,%7}, {%8,%9}, {%0,%1,%2,%3};"
        : "+f"(c[0]), "+f"(c[1]), "+f"(c[2]), "+f"(c[3])
        : "r"(a[0]), "r"(a[1]), "r"(a[2]), "r"(a[3]), "r"(b[0]), "r"(b[1]));
}
__device__ __forceinline__ unsigned smem_u32(const void* p) {
    return (unsigned)__cvta_generic_to_shared(p);
}
#define CP16(dst, src) asm volatile("cp.async.cg.shared.global [%0], [%1], 16;" :: "r"(dst), "l"(src))
#define CP_COMMIT()    asm volatile("cp.async.commit_group;")
#define CP_WAIT1()     asm volatile("cp.async.wait_group 1;")
#define CP_WAIT0()     asm volatile("cp.async.wait_group 0;")

// ---------------- fp32 -> fp16 bulk convert ----------------
__global__ __launch_bounds__(256) void f2h_kernel(
    const float4* __restrict__ in, uint2* __restrict__ out, int n4)
{
    int i = blockIdx.x * 256 + threadIdx.x;
    if (i >= n4) return;
    float4 v = in[i];
    __half2 h0 = __floats2half2_rn(v.x, v.y);
    __half2 h1 = __floats2half2_rn(v.z, v.w);
    uint2 o;
    o.x = *reinterpret_cast<unsigned*>(&h0);
    o.y = *reinterpret_cast<unsigned*>(&h1);
    out[i] = o;
}

// ---------------- W -> k-paired fp16 layout ----------------
__global__ __launch_bounds__(256) void wpair_kernel(
    const float* __restrict__ W, __half* __restrict__ Wp, int K, int N)
{
    int idx = blockIdx.x * 256 + threadIdx.x;
    if (idx >= K * N) return;
    int k = idx / N, n = idx - k * N;
    Wp[((size_t)(k >> 1) * N + n) * 2 + (k & 1)] = __float2half(W[idx]);
}

// ---------------- [Wq|Wk|Wv] -> combined k-paired fp16 ----------------
__global__ __launch_bounds__(256) void wqkv_pair_kernel(
    const float* __restrict__ Wq, const float* __restrict__ Wk,
    const float* __restrict__ Wv, __half2* __restrict__ WC)
{
    int idx = blockIdx.x * 256 + threadIdx.x;
    if (idx >= 32 * 128) return;
    int kk = idx >> 7, c = idx & 127;
    float lo, hi;
    if (c < 32)      { lo = Wq[(2 * kk) * SL + c];        hi = Wq[(2 * kk + 1) * SL + c]; }
    else if (c < 64) { lo = Wk[(2 * kk) * SL + (c - 32)]; hi = Wk[(2 * kk + 1) * SL + (c - 32)]; }
    else             { lo = Wv[(2 * kk) * DH + (c - 64)]; hi = Wv[(2 * kk + 1) * DH + (c - 64)]; }
    WC[idx] = __floats2half2_rn(lo, hi);
}

// ================= Fused GEMM1 + kvq =================
// grid (4 colblocks, 512 rowblocks), 256 threads, dynamic smem.
// Phase 1: 128x128 GEMM tile of x@W_in+b_in (K=512) -> fp16 in smem (Xall).
// Phase 2: warps 0-3 run kvq for head 2cb, warps 4-7 for head 2cb+1 (this rowblock = one split).
//
// smem layout (bytes):
//   [0, 20992)      GEMM stages: AsH 2x128x24 half (12288) + Bs 2x8x136 half2 (8704)
//                   -> aliased by WCs stage [32 rows x 136 half2, row stride 544B] after GEMM
//   [20992, 55808)  Xall [128][136] half
//   [55808, 83456)  per-head Es[32*72 half = 4608B] + Vsp[9216B] : 13824 per head x2
//   [83456, 101888) per-head Qs [64*36 float = 9216B] x2
#define G1KVQ_SMEM 101888

__global__ __launch_bounds__(256) void g1kvq_kernel(
    const __half* __restrict__ xh, const __half2* __restrict__ Wp,
    const float* __restrict__ b_in, const __half2* __restrict__ WC)
{
    extern __shared__ char sm[];
    __half*   AsH  = reinterpret_cast<__half*>(sm);
    __half2*  Bs2  = reinterpret_cast<__half2*>(sm + 12288);
    const unsigned* BsW  = reinterpret_cast<const unsigned*>(sm + 12288);
    const unsigned* WCsW = reinterpret_cast<const unsigned*>(sm);          // alias post-GEMM
    __half*   XallH = reinterpret_cast<__half*>(sm + 20992);

    const int tid  = threadIdx.x;
    const int warp = tid >> 5;
    const int lane = tid & 31;
    const int g = lane >> 2;
    const int t = lane & 3;

    const int rowBase = blockIdx.y * 128;
    const int colBase = blockIdx.x * 128;
    const int wm = (warp & 3) * 32;
    const int wn = (warp >> 2) * 64;

    // ---------------- Phase 1: GEMM (round-13 proven structure) ----------------
    float acc[2][8][4];
#pragma unroll
    for (int mt = 0; mt < 2; mt++)
#pragma unroll
        for (int nt = 0; nt < 8; nt++)
#pragma unroll
            for (int i = 0; i < 4; i++) acc[mt][nt][i] = 0.f;

    const int aRow = tid >> 1;
    const int aOff = (tid & 1) * 8;
    const int bKK  = tid >> 5;
    const int bN4  = (tid & 31) * 4;

    const __half*  Ag = xh + (size_t)(rowBase + aRow) * DIM + aOff;
    const __half2* Bg = Wp + (size_t)bKK * 512 + colBase + bN4;

    unsigned sA = smem_u32(AsH + aRow * 24 + aOff);
    unsigned sB = smem_u32(Bs2 + bKK * 136 + bN4);
    const unsigned strideA = 128 * 24 * 2;
    const unsigned strideB = 8 * 136 * 4;

    CP16(sA, Ag);
    CP16(sB, Bg);
    CP_COMMIT();

    const int nIter = DIM >> 4;   // 32
#pragma unroll 1
    for (int it = 0; it < nIter; it++) {
        const int kt = it * 16;
        const int cur = it & 1;
        if (it + 1 < nIter) {
            const unsigned offA = (cur ^ 1) ? strideA : 0;
            const unsigned offB = (cur ^ 1) ? strideB : 0;
            CP16(sA + offA, Ag + kt + 16);
            CP16(sB + offB, Bg + (size_t)(it + 1) * 8 * 512);
            CP_COMMIT();
            CP_WAIT1();
        } else {
            CP_WAIT0();
        }
        __syncthreads();

        unsigned af[2][4], bf[8][2];
#pragma unroll
        for (int mt = 0; mt < 2; mt++) {
            const int r0 = wm + mt * 16 + g;
            af[mt][0] = *reinterpret_cast<const unsigned*>(&AsH[(cur * 128 + r0    ) * 24 + 2 * t    ]);
            af[mt][1] = *reinterpret_cast<const unsigned*>(&AsH[(cur * 128 + r0 + 8) * 24 + 2 * t    ]);
            af[mt][2] = *reinterpret_cast<const unsigned*>(&AsH[(cur * 128 + r0    ) * 24 + 2 * t + 8]);
            af[mt][3] = *reinterpret_cast<const unsigned*>(&AsH[(cur * 128 + r0 + 8) * 24 + 2 * t + 8]);
        }
#pragma unroll
        for (int nt = 0; nt < 8; nt++) {
            const int c0 = wn + nt * 8 + g;
            bf[nt][0] = BsW[(cur * 8 + t    ) * 136 + c0];
            bf[nt][1] = BsW[(cur * 8 + t + 4) * 136 + c0];
        }
#pragma unroll
        for (int mt = 0; mt < 2; mt++)
#pragma unroll
            for (int nt = 0; nt < 8; nt++)
                mma_f16(acc[mt][nt], af[mt], bf[nt]);
        __syncthreads();
    }
    // GEMM smem region now dead (final sync above) -> stage WC into it, overlapping epilogue
    {
        const unsigned WCsBase = smem_u32(sm);
#pragma unroll
        for (int i = 0; i < 4; i++) {
            int idx = tid + i * 256;            // 0..1023
            int row = idx >> 5, seg = idx & 31;
            CP16(WCsBase + row * 544 + seg * 16, WC + row * 128 + seg * 4);
        }
        CP_COMMIT();
    }

    // epilogue: acc + bias -> fp16 Xall (bitwise identical to old xmid values)
#pragma unroll
    for (int nt = 0; nt < 8; nt++) {
        const int c0 = wn + nt * 8 + 2 * t;
        const float bx = b_in[colBase + c0], by = b_in[colBase + c0 + 1];
#pragma unroll
        for (int mt = 0; mt < 2; mt++) {
            const int r0 = wm + mt * 16 + g;
            __half2 h0 = __floats2half2_rn(acc[mt][nt][0] + bx, acc[mt][nt][1] + by);
            __half2 h1 = __floats2half2_rn(acc[mt][nt][2] + bx, acc[mt][nt][3] + by);
            *reinterpret_cast<__half2*>(&XallH[(r0    ) * 136 + c0]) = h0;
            *reinterpret_cast<__half2*>(&XallH[(r0 + 8) * 136 + c0]) = h1;
        }
    }
    CP_WAIT0();
    __syncthreads();   // Xall + WCs both resident

    // ---------------- Phase 2: kvq, two head-groups of 4 warps ----------------
    const int wg  = tid >> 7;          // 0 or 1 -> head within colblock
    const int wgt = tid & 127;
    const int w4  = wgt >> 5;          // warp within group
    const int hsel = 2 * blockIdx.x + wg;
    const int b    = rowBase >> 13;            // / SEQ
    const int split = (rowBase & (SEQ - 1)) >> 7;
    const int bh   = b * HEADS + hsel;

    __half* Es   = reinterpret_cast<__half*>(sm + 55808 + wg * 13824);
    __half* VspH = Es + 2304;
    const unsigned* VspW = reinterpret_cast<const unsigned*>(VspH);
    float*  Qs   = reinterpret_cast<float*>(sm + 83456 + wg * 9216);

    // weight B-fragments (shared WCs, per-group warp cols)
    unsigned bfw[4][4][2];
#pragma unroll
    for (int nt = 0; nt < 4; nt++)
#pragma unroll
        for (int ks = 0; ks < 4; ks++) {
            const int c0 = 32 * w4 + nt * 8 + g;
            bfw[nt][ks][0] = WCsW[(8 * ks + t    ) * 136 + c0];
            bfw[nt][ks][1] = WCsW[(8 * ks + t + 4) * 136 + c0];
        }

    float accS1[2][2][4];
#pragma unroll
    for (int mt = 0; mt < 2; mt++)
#pragma unroll
        for (int nt = 0; nt < 2; nt++)
#pragma unroll
            for (int i = 0; i < 4; i++) accS1[mt][nt][i] = 0.f;
    float s0acc = 0.f;

#pragma unroll 1
    for (int chunk = 0; chunk < 2; chunk++) {
        const __half* Xc = XallH + (chunk * 64) * 136 + wg * 64;

#pragma unroll
        for (int mt = 0; mt < 4; mt++) {
            float pacc[4][4];
#pragma unroll
            for (int nt = 0; nt < 4; nt++)
#pragma unroll
                for (int i = 0; i < 4; i++) pacc[nt][i] = 0.f;

#pragma unroll
            for (int ks = 0; ks < 4; ks++) {
                const int r0 = mt * 16 + g;
                unsigned af[4];
                af[0] = *reinterpret_cast<const unsigned*>(&Xc[(r0    ) * 136 + 16 * ks + 2 * t    ]);
                af[1] = *reinterpret_cast<const unsigned*>(&Xc[(r0 + 8) * 136 + 16 * ks + 2 * t    ]);
                af[2] = *reinterpret_cast<const unsigned*>(&Xc[(r0    ) * 136 + 16 * ks + 2 * t + 8]);
                af[3] = *reinterpret_cast<const unsigned*>(&Xc[(r0 + 8) * 136 + 16 * ks + 2 * t + 8]);
#pragma unroll
                for (int nt = 0; nt < 4; nt++)
                    mma_f16(pacc[nt], af, bfw[nt][ks]);
            }

#pragma unroll
            for (int nt = 0; nt < 4; nt++) {
                const int c0 = 32 * w4 + nt * 8 + 2 * t;
                const int r0 = mt * 16 + g;
                float v0 = pacc[nt][0], v1 = pacc[nt][1];
                float v2 = pacc[nt][2], v3 = pacc[nt][3];
                if (w4 == 0) {
                    Qs[(r0    ) * 36 + c0]     = v0;
                    Qs[(r0    ) * 36 + c0 + 1] = v1;
                    Qs[(r0 + 8) * 36 + c0]     = v2;
                    Qs[(r0 + 8) * 36 + c0 + 1] = v3;
                } else if (w4 == 1) {
                    const int s = c0 - 32;
                    Es[(s    ) * 72 + r0]     = __float2half(expf(v0));
                    Es[(s + 1) * 72 + r0]     = __float2half(expf(v1));
                    Es[(s    ) * 72 + r0 + 8] = __float2half(expf(v2));
                    Es[(s + 1) * 72 + r0 + 8] = __float2half(expf(v3));
                } else {
                    const int c = c0 - 64;
                    VspH[(r0 >> 1) * 144 + c * 2 + (r0 & 1)]                   = __float2half(v0);
                    VspH[(r0 >> 1) * 144 + (c + 1) * 2 + (r0 & 1)]             = __float2half(v1);
                    VspH[((r0 + 8) >> 1) * 144 + c * 2 + ((r0 + 8) & 1)]       = __float2half(v2);
                    VspH[((r0 + 8) >> 1) * 144 + (c + 1) * 2 + ((r0 + 8) & 1)] = __float2half(v3);
                }
            }
        }
        __syncthreads();

        // softmax (one token per thread in group) + S0 column sums
        if (wgt < 64) {
            float m = Qs[wgt * 36 + 0];
#pragma unroll
            for (int s = 1; s < 32; s++) m = fmaxf(m, Qs[wgt * 36 + s]);
            float e[32], sum = 0.f;
#pragma unroll
            for (int s = 0; s < 32; s++) { e[s] = expf(Qs[wgt * 36 + s] - m); sum += e[s]; }
            float inv = 1.f / sum;
#pragma unroll
            for (int s = 0; s < 32; s++) Qs[wgt * 36 + s] = e[s] * inv;
        } else if (wgt < 96) {
            const int s = wgt - 64;
            const __half2* Erow = reinterpret_cast<const __half2*>(&Es[s * 72]);
            float acc0 = 0.f;
#pragma unroll
            for (int r2 = 0; r2 < 32; r2++) {
                float2 f = __half22float2(Erow[r2]);
                acc0 += f.x + f.y;
            }
            s0acc += acc0;
        }
        __syncthreads();

        // fp16 store of softmaxed Q
        const int n0 = rowBase + chunk * 64;
        for (int idx = wgt; idx < 64 * 8; idx += 128) {
            int r = idx >> 3, c4 = (idx & 7) * 4;
            float4 v = *reinterpret_cast<const float4*>(&Qs[r * 36 + c4]);
            __half2 h0 = __floats2half2_rn(v.x, v.y);
            __half2 h1 = __floats2half2_rn(v.z, v.w);
            uint2 o;
            o.x = *reinterpret_cast<unsigned*>(&h0);
            o.y = *reinterpret_cast<unsigned*>(&h1);
            *reinterpret_cast<uint2*>(
                &g_qh[(size_t)(n0 + r) * QDIM + hsel * SL + c4]) = o;
        }

        // S1 += Es(32 x 64tok) @ V(64tok x 64)
#pragma unroll
        for (int ks = 0; ks < 4; ks++) {
            unsigned af2[2][4];
#pragma unroll
            for (int mt = 0; mt < 2; mt++) {
                const int r0 = mt * 16 + g;
                af2[mt][0] = *reinterpret_cast<const unsigned*>(&Es[(r0    ) * 72 + 16 * ks + 2 * t    ]);
                af2[mt][1] = *reinterpret_cast<const unsigned*>(&Es[(r0 + 8) * 72 + 16 * ks + 2 * t    ]);
                af2[mt][2] = *reinterpret_cast<const unsigned*>(&Es[(r0    ) * 72 + 16 * ks + 2 * t + 8]);
                af2[mt][3] = *reinterpret_cast<const unsigned*>(&Es[(r0 + 8) * 72 + 16 * ks + 2 * t + 8]);
            }
#pragma unroll
            for (int nt = 0; nt < 2; nt++) {
                const int c0 = 16 * w4 + nt * 8 + g;
                unsigned bf2[2];
                bf2[0] = VspW[(8 * ks + t    ) * 72 + c0];
                bf2[1] = VspW[(8 * ks + t + 4) * 72 + c0];
#pragma unroll
                for (int mt = 0; mt < 2; mt++)
                    mma_f16(accS1[mt][nt], af2[mt], bf2);
            }
        }
        __syncthreads();   // Es/Vsp consumed before next chunk overwrites
    }

    float* base = g_S1p + ((size_t)split * 64 + bh) * (SL * DH);
#pragma unroll
    for (int mt = 0; mt < 2; mt++)
#pragma unroll
        for (int nt = 0; nt < 2; nt++) {
            const int s0 = mt * 16 + g;
            const int c  = 16 * w4 + nt * 8 + 2 * t;
            base[(s0    ) * DH + c]     = accS1[mt][nt][0];
            base[(s0    ) * DH + c + 1] = accS1[mt][nt][1];
            base[(s0 + 8) * DH + c]     = accS1[mt][nt][2];
            base[(s0 + 8) * DH + c + 1] = accS1[mt][nt][3];
        }
    if (wgt >= 64 && wgt < 96)
        g_S0p[((size_t)split * 64 + bh) * SL + (wgt - 64)] = s0acc;
}

// ---------------- Merged kv-finalize + Z prep (validated) ----------------
__global__ __launch_bounds__(512) void kvz_kernel(const float* __restrict__ W_out)
{
    __shared__ float kvs[SL][DH];
    __shared__ float s0s[SL];
    __shared__ float Wos[DH][128];

    const int h = blockIdx.x;
    const int b = blockIdx.y;
    const int bh = b * HEADS + h;
    const int tid = threadIdx.x;

    if (tid < SL) {
        float s0 = 0.f;
        for (int sp = 0; sp < KV_SPLITS; sp++)
            s0 += g_S0p[((size_t)sp * 64 + bh) * SL + tid];
        s0s[tid] = s0;
    }

    float s1v[4] = {0.f, 0.f, 0.f, 0.f};
    for (int sp = 0; sp < KV_SPLITS; sp++) {
        const float* p = g_S1p + ((size_t)sp * 64 + bh) * (SL * DH);
#pragma unroll
        for (int j = 0; j < 4; j++) s1v[j] += p[tid + j * 512];
    }
    __syncthreads();
#pragma unroll
    for (int j = 0; j < 4; j++) {
        int i = tid + j * 512;
        reinterpret_cast<float*>(kvs)[i] = s1v[j] / s0s[i >> 6];
    }
    __syncthreads();

#pragma unroll 1
    for (int cb = 0; cb < 4; cb++) {
        for (int i = tid; i < DH * 32; i += 512) {
            int k = i >> 5, c4 = (i & 31) * 4;
            *reinterpret_cast<float4*>(&Wos[k][c4]) =
                *reinterpret_cast<const float4*>(
                    &W_out[(size_t)(h * DH + k) * DIM + cb * 128 + c4]);
        }
        __syncthreads();

        for (int i = tid; i < SL * 128; i += 512) {
            int s = i >> 7, c = i & 127;
            float d = 0.f;
#pragma unroll
            for (int k = 0; k < DH; k++) d = fmaf(kvs[s][k], Wos[k][c], d);
            const int kidx = h * SL + s;
            const int n    = cb * 128 + c;
            g_Zp[(size_t)b * QDIM * DIM + ((size_t)(kidx >> 1) * DIM + n) * 2 + (kidx & 1)]
                = __float2half(d);
        }
        __syncthreads();
    }
}

// ---------------- GEMM2: out = Q @ Z_b + b_out (round-13 proven, fp32 out) ----------------
__global__ __launch_bounds__(256) void h16gemm2_kernel(
    const __half* __restrict__ A, const __half2* __restrict__ Bp,
    const float* __restrict__ bias, float* __restrict__ C, int K,
    size_t zStrideA, size_t zStrideB, size_t zStrideC)
{
    const int N = 512;
    __shared__ __half  As[2][128][24];
    __shared__ __half2 Bs[2][8][136];

    const int tid  = threadIdx.x;
    const int warp = tid >> 5;
    const int lane = tid & 31;
    const int g = lane >> 2;
    const int t = lane & 3;

    const int rowBase = blockIdx.y * 128;
    const int colBase = blockIdx.x * 128;
    const int wm = (warp & 3) * 32;
    const int wn = (warp >> 2) * 64;

    A  += zStrideA * blockIdx.z;
    Bp += zStrideB * blockIdx.z;
    C  += zStrideC * blockIdx.z;

    float acc[2][8][4];
#pragma unroll
    for (int mt = 0; mt < 2; mt++)
#pragma unroll
        for (int nt = 0; nt < 8; nt++)
#pragma unroll
            for (int i = 0; i < 4; i++) acc[mt][nt][i] = 0.f;

    const int aRow = tid >> 1;
    const int aOff = (tid & 1) * 8;
    const int bKK  = tid >> 5;
    const int bN4  = (tid & 31) * 4;

    const __half*  Ag = A + (size_t)(rowBase + aRow) * K + aOff;
    const __half2* Bg = Bp + (size_t)bKK * N + colBase + bN4;

    unsigned sA = smem_u32(&As[0][aRow][aOff]);
    unsigned sB = smem_u32(&Bs[0][bKK][bN4]);
    const unsigned strideA = 128 * 24 * 2;
    const unsigned strideB = 8 * 136 * 4;

    CP16(sA, Ag);
    CP16(sB, Bg);
    CP_COMMIT();

    const int nIter = K >> 4;
#pragma unroll 1
    for (int it = 0; it < nIter; it++) {
        const int kt = it * 16;
        const int cur = it & 1;
        if (it + 1 < nIter) {
            const unsigned offA = (cur ^ 1) ? strideA : 0;
            const unsigned offB = (cur ^ 1) ? strideB : 0;
            CP16(sA + offA, Ag + kt + 16);
            CP16(sB + offB, Bg + (size_t)(it + 1) * 8 * N);
            CP_COMMIT();
            CP_WAIT1();
        } else {
            CP_WAIT0();
        }
        __syncthreads();

        unsigned af[2][4], bf[8][2];
#pragma unroll
        for (int mt = 0; mt < 2; mt++) {
            const int r0 = wm + mt * 16 + g;
            af[mt][0] = *reinterpret_cast<const unsigned*>(&As[cur][r0    ][2 * t    ]);
            af[mt][1] = *reinterpret_cast<const unsigned*>(&As[cur][r0 + 8][2 * t    ]);
            af[mt][2] = *reinterpret_cast<const unsigned*>(&As[cur][r0    ][2 * t + 8]);
            af[mt][3] = *reinterpret_cast<const unsigned*>(&As[cur][r0 + 8][2 * t + 8]);
        }
#pragma unroll
        for (int nt = 0; nt < 8; nt++) {
            const int c0 = wn + nt * 8 + g;
            bf[nt][0] = *reinterpret_cast<const unsigned*>(&Bs[cur][t    ][c0]);
            bf[nt][1] = *reinterpret_cast<const unsigned*>(&Bs[cur][t + 4][c0]);
        }
#pragma unroll
        for (int mt = 0; mt < 2; mt++)
#pragma unroll
            for (int nt = 0; nt < 8; nt++)
                mma_f16(acc[mt][nt], af[mt], bf[nt]);
        __syncthreads();
    }

#pragma unroll
    for (int nt = 0; nt < 8; nt++) {
        const int col = colBase + wn + nt * 8 + 2 * t;
        const float bx = bias[col], by = bias[col + 1];
#pragma unroll
        for (int mt = 0; mt < 2; mt++) {
            const int row0 = rowBase + wm + mt * 16 + g;
            float2 o0, o1;
            o0.x = acc[mt][nt][0] + bx; o0.y = acc[mt][nt][1] + by;
            o1.x = acc[mt][nt][2] + bx; o1.y = acc[mt][nt][3] + by;
            *reinterpret_cast<float2*>(&C[(size_t)row0 * N + col])       = o0;
            *reinterpret_cast<float2*>(&C[(size_t)(row0 + 8) * N + col]) = o1;
        }
    }
}

// ---------------- launch ----------------
extern "C" void kernel_launch(void* const* d_in, const int* in_sizes, int n_in,
                              void* d_out, int out_size)
{
    const float* x     = (const float*)d_in[0];
    const float* W_in  = (const float*)d_in[1];
    const float* b_in  = (const float*)d_in[2];
    const float* Wq    = (const float*)d_in[3];
    const float* Wk    = (const float*)d_in[4];
    const float* Wv    = (const float*)d_in[5];
    const float* W_out = (const float*)d_in[6];
    const float* b_out = (const float*)d_in[7];
    float* out = (float*)d_out;

    __half *xh, *qh, *Wp, *Zp;
    __half2* WC;
    cudaGetSymbolAddress((void**)&xh, g_xh);
    cudaGetSymbolAddress((void**)&qh, g_qh);
    cudaGetSymbolAddress((void**)&Wp, g_Wp);
    cudaGetSymbolAddress((void**)&Zp, g_Zp);
    cudaGetSymbolAddress((void**)&WC, g_WC);

    cudaFuncSetAttribute(g1kvq_kernel,
                         cudaFuncAttributeMaxDynamicSharedMemorySize, G1KVQ_SMEM);

    // 0) conversions
    const int n4 = MTOT * DIM / 4;
    f2h_kernel<<<(n4 + 255) / 256, 256>>>((const float4*)x, (uint2*)xh, n4);
    wpair_kernel<<<(DIM * DIM + 255) / 256, 256>>>(W_in, Wp, DIM, DIM);
    wqkv_pair_kernel<<<(32 * 128 + 255) / 256, 256>>>(Wq, Wk, Wv, WC);

    // 1) fused GEMM1 + kvq: q-softmax -> g_qh, kv split partials (no xmid round-trip)
    dim3 g1(DIM / 128, MTOT / 128);
    g1kvq_kernel<<<g1, 256, G1KVQ_SMEM>>>(xh, (const __half2*)Wp, b_in, (const __half2*)WC);

    // 2) merged kv finalize + Z prep
    dim3 zGrid(HEADS, BATCH);
    kvz_kernel<<<zGrid, 512>>>(W_out);

    // 3) out = Q @ Z_b + b_out   (fp16 mma, K=256, batched; fp32 output)
    dim3 g2(DIM / 128, SEQ / 128, BATCH);
    h16gemm2_kernel<<<g2, 256>>>(qh, (const __half2*)Zp, b_out, out, QDIM,
                                 (size_t)SEQ * QDIM,
                                 (size_t)QDIM * DIM / 2,
                                 (size_t)SEQ * DIM);
}